// round 16
// baseline (speedup 1.0000x reference)
#include <cuda_runtime.h>

#define Bn 8
#define Sn 1024
#define Cn 512
#define NH 8
#define HDm 64
#define Gn 32
#define CPG 16
#define MROWS (Bn*Sn)          /* 8192 */
#define QKVN (3*NH*HDm)        /* 1536 */

// Scratch (allocation-free requirement: __device__ globals)
__device__ float g_qkv[(size_t)MROWS * QKVN];   // 50.3 MB
__device__ float g_attn[(size_t)MROWS * Cn];    // 16.8 MB

// ---------------------------------------------------------------------------
// Kernel 1: GroupNorm. grid = B*G blocks, 256 threads. Writes xn -> out.
// ---------------------------------------------------------------------------
__global__ void gn_kernel(const float* __restrict__ x,
                          const float* __restrict__ scale,
                          const float* __restrict__ bias,
                          float* __restrict__ xn)
{
    const int b = blockIdx.x / Gn;
    const int g = blockIdx.x % Gn;
    const int N = Sn * CPG;               // 16384 elements per (b, group)
    const float4* x4 = (const float4*)x;
    float4* o4 = (float4*)xn;
    const size_t baseq = ((size_t)b * Sn * Cn + (size_t)g * CPG) >> 2;

    float s = 0.f, s2 = 0.f;
    for (int i = threadIdx.x; i < N / 4; i += blockDim.x) {
        int p = i >> 2, c4 = i & 3;
        float4 v = x4[baseq + (size_t)p * (Cn / 4) + c4];
        s  += v.x + v.y + v.z + v.w;
        s2 += v.x * v.x + v.y * v.y + v.z * v.z + v.w * v.w;
    }
    #pragma unroll
    for (int off = 16; off; off >>= 1) {
        s  += __shfl_down_sync(0xffffffffu, s,  off);
        s2 += __shfl_down_sync(0xffffffffu, s2, off);
    }
    __shared__ float ws[8], ws2[8];
    __shared__ float sh_mean, sh_inv;
    int wid = threadIdx.x >> 5, lane = threadIdx.x & 31;
    if (lane == 0) { ws[wid] = s; ws2[wid] = s2; }
    __syncthreads();
    if (threadIdx.x == 0) {
        float ts = 0.f, ts2 = 0.f;
        #pragma unroll
        for (int i = 0; i < 8; i++) { ts += ws[i]; ts2 += ws2[i]; }
        float mean = ts / (float)N;
        float var  = ts2 / (float)N - mean * mean;
        sh_mean = mean;
        sh_inv  = rsqrtf(var + 1e-5f);
    }
    __syncthreads();
    const float mean = sh_mean, inv = sh_inv;

    for (int i = threadIdx.x; i < N / 4; i += blockDim.x) {
        int p = i >> 2, c4 = i & 3;
        float4 v  = x4[baseq + (size_t)p * (Cn / 4) + c4];
        float4 sc = *(const float4*)&scale[g * CPG + c4 * 4];
        float4 bi = *(const float4*)&bias [g * CPG + c4 * 4];
        float4 r;
        r.x = (v.x - mean) * inv * sc.x + bi.x;
        r.y = (v.y - mean) * inv * sc.y + bi.y;
        r.z = (v.z - mean) * inv * sc.z + bi.z;
        r.w = (v.w - mean) * inv * sc.w + bi.w;
        o4[baseq + (size_t)p * (Cn / 4) + c4] = r;
    }
}

// ---------------------------------------------------------------------------
// Kernel 2/4: tiled SGEMM  C = A[MxK] @ W[KxN] + bias (+ residual).
// 64x64 block tile, BK=16, 256 threads, 4x4 per-thread microkernel.
// Dims are multiples of tile sizes (8192, 1536/512, 512) -> no bounds checks.
// ---------------------------------------------------------------------------
template <bool RES>
__global__ void __launch_bounds__(256)
sgemm_kernel(const float* __restrict__ A,
             const float* __restrict__ W,
             const float* __restrict__ bias,
             const float* __restrict__ res,
             float* __restrict__ Cm,
             int M, int N, int K)
{
    __shared__ float As[16][64];   // transposed A tile: As[k][m]
    __shared__ float Bs[16][64];   // Bs[k][n]

    const int t  = threadIdx.x;
    const int tx = t & 15;         // 0..15 -> 4 cols each
    const int ty = t >> 4;         // 0..15 -> 4 rows each
    const int rowBase = blockIdx.y * 64;
    const int colBase = blockIdx.x * 64;

    const int ar  = t >> 2;          // 0..63 row within A tile
    const int ak  = (t & 3) << 2;    // 0,4,8,12 k-offset
    const int brk = t >> 4;          // 0..15 k row of B tile
    const int bc  = (t & 15) << 2;   // 0..60 col

    const float* Aptr = A + (size_t)(rowBase + ar) * K + ak;
    const float* Bptr = W + (size_t)brk * N + colBase + bc;

    float acc[4][4] = {};

    for (int k0 = 0; k0 < K; k0 += 16) {
        float4 a = *(const float4*)(Aptr + k0);
        As[ak + 0][ar] = a.x;
        As[ak + 1][ar] = a.y;
        As[ak + 2][ar] = a.z;
        As[ak + 3][ar] = a.w;
        *(float4*)&Bs[brk][bc] = *(const float4*)(Bptr + (size_t)k0 * N);
        __syncthreads();

        #pragma unroll
        for (int k = 0; k < 16; k++) {
            float4 a4 = *(float4*)&As[k][ty << 2];
            float4 b4 = *(float4*)&Bs[k][tx << 2];
            float ra[4] = {a4.x, a4.y, a4.z, a4.w};
            float rb[4] = {b4.x, b4.y, b4.z, b4.w};
            #pragma unroll
            for (int i = 0; i < 4; i++)
                #pragma unroll
                for (int j = 0; j < 4; j++)
                    acc[i][j] += ra[i] * rb[j];
        }
        __syncthreads();
    }

    float4 bv = *(const float4*)&bias[colBase + (tx << 2)];
    float bb[4] = {bv.x, bv.y, bv.z, bv.w};
    #pragma unroll
    for (int i = 0; i < 4; i++) {
        size_t ro = (size_t)(rowBase + (ty << 2) + i) * N + colBase + (tx << 2);
        float4 r;
        r.x = acc[i][0] + bb[0];
        r.y = acc[i][1] + bb[1];
        r.z = acc[i][2] + bb[2];
        r.w = acc[i][3] + bb[3];
        if (RES) {
            float4 rv = *(const float4*)&res[ro];
            r.x += rv.x; r.y += rv.y; r.z += rv.z; r.w += rv.w;
        }
        *(float4*)&Cm[ro] = r;
    }
}

// ---------------------------------------------------------------------------
// Kernel 3: flash-style attention. One query per thread; q/o in registers;
// K/V tiles (64 keys) streamed through smem; online softmax with rare rescale.
// grid = B*NH*(S/128) = 512 blocks of 128 threads.
// ---------------------------------------------------------------------------
__global__ void __launch_bounds__(128)
attn_kernel()
{
    const int T = 64;                         // key tile
    const int chunks = Sn / 128;              // 8
    const int bh = blockIdx.x / chunks;       // 0..63
    const int qc = blockIdx.x % chunks;
    const int b = bh >> 3, h = bh & 7;
    const int qrow = qc * 128 + threadIdx.x;

    const float* base = g_qkv + (size_t)b * Sn * QKVN + h * (3 * HDm);

    float q[64];
    {
        const float4* qp = (const float4*)(base + (size_t)qrow * QKVN);
        #pragma unroll
        for (int c = 0; c < 16; c++) {
            float4 v = qp[c];
            q[4*c+0] = v.x * 0.125f;   // 1/sqrt(64)
            q[4*c+1] = v.y * 0.125f;
            q[4*c+2] = v.z * 0.125f;
            q[4*c+3] = v.w * 0.125f;
        }
    }
    float o[64];
    #pragma unroll
    for (int d = 0; d < 64; d++) o[d] = 0.f;
    float m = -1e30f, l = 0.f;

    __shared__ float4 Ks[T * 16];
    __shared__ float4 Vs[T * 16];

    for (int k0 = 0; k0 < Sn; k0 += T) {
        for (int i = threadIdx.x; i < T * 16; i += 128) {
            int r = i >> 4, c = i & 15;
            const float4* kp = (const float4*)(base + (size_t)(k0 + r) * QKVN + HDm);
            Ks[i] = kp[c];        // K at cols [64,128)
            Vs[i] = kp[16 + c];   // V at cols [128,192)
        }
        __syncthreads();

        for (int j = 0; j < T; j++) {
            float s = 0.f;
            #pragma unroll
            for (int c = 0; c < 16; c++) {
                float4 kv = Ks[j * 16 + c];   // broadcast across warp
                s += q[4*c+0] * kv.x + q[4*c+1] * kv.y
                   + q[4*c+2] * kv.z + q[4*c+3] * kv.w;
            }
            if (s > m) {                       // rare rescale path
                float corr = __expf(m - s);
                l *= corr;
                #pragma unroll
                for (int d = 0; d < 64; d++) o[d] *= corr;
                m = s;
            }
            float p = __expf(s - m);
            l += p;
            #pragma unroll
            for (int c = 0; c < 16; c++) {
                float4 v4 = Vs[j * 16 + c];
                o[4*c+0] += p * v4.x;
                o[4*c+1] += p * v4.y;
                o[4*c+2] += p * v4.z;
                o[4*c+3] += p * v4.w;
            }
        }
        __syncthreads();
    }

    const float invl = 1.f / l;
    float4* op = (float4*)(g_attn + (size_t)(b * Sn + qrow) * Cn + h * HDm);
    #pragma unroll
    for (int c = 0; c < 16; c++) {
        float4 r;
        r.x = o[4*c+0] * invl;
        r.y = o[4*c+1] * invl;
        r.z = o[4*c+2] * invl;
        r.w = o[4*c+3] * invl;
        op[c] = r;
    }
}

// ---------------------------------------------------------------------------
// Launch: gn -> qkv gemm -> attention -> out gemm (+bias +residual)
// ---------------------------------------------------------------------------
extern "C" void kernel_launch(void* const* d_in, const int* in_sizes, int n_in,
                              void* d_out, int out_size)
{
    const float* x        = (const float*)d_in[0];
    // d_in[1] = t, unused by the reference computation
    const float* gn_scale = (const float*)d_in[2];
    const float* gn_bias  = (const float*)d_in[3];
    const float* w_qkv    = (const float*)d_in[4];
    const float* b_qkv    = (const float*)d_in[5];
    const float* w_out    = (const float*)d_in[6];
    const float* b_out    = (const float*)d_in[7];
    float* out = (float*)d_out;

    float *qkv_p = nullptr, *attn_p = nullptr;
    cudaGetSymbolAddress((void**)&qkv_p,  g_qkv);
    cudaGetSymbolAddress((void**)&attn_p, g_attn);

    // 1) GroupNorm -> xn lives in d_out (used as GEMM-A input and as residual)
    gn_kernel<<<Bn * Gn, 256>>>(x, gn_scale, gn_bias, out);

    // 2) QKV projection: [8192,512] @ [512,1536] + b_qkv
    {
        dim3 grid(QKVN / 64, MROWS / 64);
        sgemm_kernel<false><<<grid, 256>>>(out, w_qkv, b_qkv, nullptr, qkv_p,
                                           MROWS, QKVN, Cn);
    }

    // 3) Attention: g_qkv -> g_attn [8192,512]
    attn_kernel<<<Bn * NH * (Sn / 128), 128>>>();

    // 4) Output projection + bias + residual(xn) -> d_out
    {
        dim3 grid(Cn / 64, MROWS / 64);
        sgemm_kernel<true><<<grid, 256>>>(attn_p, w_out, b_out, out, out,
                                          MROWS, Cn, Cn);
    }
}

// round 17
// speedup vs baseline: 1.0089x; 1.0089x over previous
#include <cuda_runtime.h>

#define Bn 8
#define Sn 1024
#define Cn 512
#define NH 8
#define HDm 64
#define Gn 32
#define CPG 16
#define MROWS (Bn*Sn)          /* 8192 */
#define QKVN (3*NH*HDm)        /* 1536 */

// Scratch (allocation-free requirement: __device__ globals)
__device__ float g_qkv[(size_t)MROWS * QKVN];   // 50.3 MB
__device__ float g_attn[(size_t)MROWS * Cn];    // 16.8 MB

// ---------------------------------------------------------------------------
// Kernel 1: GroupNorm. grid = B*G blocks, 256 threads. Writes xn -> out.
// ---------------------------------------------------------------------------
__global__ void gn_kernel(const float* __restrict__ x,
                          const float* __restrict__ scale,
                          const float* __restrict__ bias,
                          float* __restrict__ xn)
{
    const int b = blockIdx.x / Gn;
    const int g = blockIdx.x % Gn;
    const int N = Sn * CPG;               // 16384 elements per (b, group)
    const float4* x4 = (const float4*)x;
    float4* o4 = (float4*)xn;
    const size_t baseq = ((size_t)b * Sn * Cn + (size_t)g * CPG) >> 2;

    float s = 0.f, s2 = 0.f;
    for (int i = threadIdx.x; i < N / 4; i += blockDim.x) {
        int p = i >> 2, c4 = i & 3;
        float4 v = x4[baseq + (size_t)p * (Cn / 4) + c4];
        s  += v.x + v.y + v.z + v.w;
        s2 += v.x * v.x + v.y * v.y + v.z * v.z + v.w * v.w;
    }
    #pragma unroll
    for (int off = 16; off; off >>= 1) {
        s  += __shfl_down_sync(0xffffffffu, s,  off);
        s2 += __shfl_down_sync(0xffffffffu, s2, off);
    }
    __shared__ float ws[8], ws2[8];
    __shared__ float sh_mean, sh_inv;
    int wid = threadIdx.x >> 5, lane = threadIdx.x & 31;
    if (lane == 0) { ws[wid] = s; ws2[wid] = s2; }
    __syncthreads();
    if (threadIdx.x == 0) {
        float ts = 0.f, ts2 = 0.f;
        #pragma unroll
        for (int i = 0; i < 8; i++) { ts += ws[i]; ts2 += ws2[i]; }
        float mean = ts / (float)N;
        float var  = ts2 / (float)N - mean * mean;
        sh_mean = mean;
        sh_inv  = rsqrtf(var + 1e-5f);
    }
    __syncthreads();
    const float mean = sh_mean, inv = sh_inv;

    for (int i = threadIdx.x; i < N / 4; i += blockDim.x) {
        int p = i >> 2, c4 = i & 3;
        float4 v  = x4[baseq + (size_t)p * (Cn / 4) + c4];
        float4 sc = *(const float4*)&scale[g * CPG + c4 * 4];
        float4 bi = *(const float4*)&bias [g * CPG + c4 * 4];
        float4 r;
        r.x = (v.x - mean) * inv * sc.x + bi.x;
        r.y = (v.y - mean) * inv * sc.y + bi.y;
        r.z = (v.z - mean) * inv * sc.z + bi.z;
        r.w = (v.w - mean) * inv * sc.w + bi.w;
        o4[baseq + (size_t)p * (Cn / 4) + c4] = r;
    }
}

// ---------------------------------------------------------------------------
// Kernel 2/4: SGEMM  C = A[MxK] @ W[KxN] + bias (+ residual).
// 128x128 block tile, BK=16, 256 threads, 8x8 microkernel, double-buffered.
// All dims are multiples of the tiles (M=8192, N in {1536,512}, K=512).
// ---------------------------------------------------------------------------
template <bool RES>
__global__ void __launch_bounds__(256, 2)
sgemm_kernel(const float* __restrict__ A,
             const float* __restrict__ W,
             const float* __restrict__ bias,
             const float* __restrict__ res,
             float* __restrict__ Cm,
             int M, int N, int K)
{
    __shared__ float As[2][16][128];   // transposed A tile: As[k][m]
    __shared__ float Bs[2][16][128];   // Bs[k][n]

    const int t  = threadIdx.x;
    const int tx = t & 15;             // 0..15 -> 8 cols each
    const int ty = t >> 4;             // 0..15 -> 8 rows each
    const int rowBase = blockIdx.y * 128;
    const int colBase = blockIdx.x * 128;

    // A load mapping: row = t&127, kq in { t>>7, (t>>7)+2 } (float4 granules)
    const int ra  = t & 127;
    const int kq0 = t >> 7;            // 0 or 1
    // B load mapping: col4 = t&31, krow in { t>>5, (t>>5)+8 }
    const int cb  = (t & 31) << 2;
    const int kr0 = t >> 5;            // 0..7

    const float* Ag = A + (size_t)(rowBase + ra) * K + (kq0 << 2);
    const float* Bg = W + (size_t)kr0 * N + colBase + cb;

    float acc[8][8] = {};

    const int NT = K / 16;
    int buf = 0;

    // prologue: tile 0 -> smem[0]
    {
        float4 a0 = *(const float4*)(Ag);
        float4 a1 = *(const float4*)(Ag + 8);
        float4 b0 = *(const float4*)(Bg);
        float4 b1 = *(const float4*)(Bg + (size_t)8 * N);
        int k4a = kq0 << 2, k4b = (kq0 + 2) << 2;
        As[0][k4a + 0][ra] = a0.x; As[0][k4a + 1][ra] = a0.y;
        As[0][k4a + 2][ra] = a0.z; As[0][k4a + 3][ra] = a0.w;
        As[0][k4b + 0][ra] = a1.x; As[0][k4b + 1][ra] = a1.y;
        As[0][k4b + 2][ra] = a1.z; As[0][k4b + 3][ra] = a1.w;
        *(float4*)&Bs[0][kr0][cb]     = b0;
        *(float4*)&Bs[0][kr0 + 8][cb] = b1;
    }
    __syncthreads();

    for (int kt = 0; kt < NT; kt++) {
        const bool hasNext = (kt + 1 < NT);
        float4 na0, na1, nb0, nb1;
        if (hasNext) {
            const float* Agn = Ag + (kt + 1) * 16;
            const float* Bgn = Bg + (size_t)(kt + 1) * 16 * N;
            na0 = *(const float4*)(Agn);
            na1 = *(const float4*)(Agn + 8);
            nb0 = *(const float4*)(Bgn);
            nb1 = *(const float4*)(Bgn + (size_t)8 * N);
        }

        #pragma unroll
        for (int k = 0; k < 16; k++) {
            float ar_[8], br_[8];
            *(float4*)&ar_[0] = *(float4*)&As[buf][k][ty << 3];
            *(float4*)&ar_[4] = *(float4*)&As[buf][k][(ty << 3) + 4];
            *(float4*)&br_[0] = *(float4*)&Bs[buf][k][tx << 3];
            *(float4*)&br_[4] = *(float4*)&Bs[buf][k][(tx << 3) + 4];
            #pragma unroll
            for (int i = 0; i < 8; i++)
                #pragma unroll
                for (int j = 0; j < 8; j++)
                    acc[i][j] += ar_[i] * br_[j];
        }

        if (hasNext) {
            int nb = buf ^ 1;
            int k4a = kq0 << 2, k4b = (kq0 + 2) << 2;
            As[nb][k4a + 0][ra] = na0.x; As[nb][k4a + 1][ra] = na0.y;
            As[nb][k4a + 2][ra] = na0.z; As[nb][k4a + 3][ra] = na0.w;
            As[nb][k4b + 0][ra] = na1.x; As[nb][k4b + 1][ra] = na1.y;
            As[nb][k4b + 2][ra] = na1.z; As[nb][k4b + 3][ra] = na1.w;
            *(float4*)&Bs[nb][kr0][cb]     = nb0;
            *(float4*)&Bs[nb][kr0 + 8][cb] = nb1;
            __syncthreads();
            buf = nb;
        }
    }

    // epilogue: bias (+ residual)
    float bb[8];
    *(float4*)&bb[0] = *(const float4*)&bias[colBase + (tx << 3)];
    *(float4*)&bb[4] = *(const float4*)&bias[colBase + (tx << 3) + 4];
    #pragma unroll
    for (int i = 0; i < 8; i++) {
        size_t ro = (size_t)(rowBase + (ty << 3) + i) * N + colBase + (tx << 3);
        float4 r0, r1;
        r0.x = acc[i][0] + bb[0]; r0.y = acc[i][1] + bb[1];
        r0.z = acc[i][2] + bb[2]; r0.w = acc[i][3] + bb[3];
        r1.x = acc[i][4] + bb[4]; r1.y = acc[i][5] + bb[5];
        r1.z = acc[i][6] + bb[6]; r1.w = acc[i][7] + bb[7];
        if (RES) {
            float4 v0 = *(const float4*)&res[ro];
            float4 v1 = *(const float4*)&res[ro + 4];
            r0.x += v0.x; r0.y += v0.y; r0.z += v0.z; r0.w += v0.w;
            r1.x += v1.x; r1.y += v1.y; r1.z += v1.z; r1.w += v1.w;
        }
        *(float4*)&Cm[ro]     = r0;
        *(float4*)&Cm[ro + 4] = r1;
    }
}

// ---------------------------------------------------------------------------
// Kernel 3: flash-style attention. One query per thread; q/o in registers;
// K/V tiles (64 keys) streamed through smem. Two keys per inner step with
// 4-way split dot accumulators (independent FFMA chains) and a single
// shared rescale per key pair.
// grid = B*NH*(S/128) = 512 blocks of 128 threads.
// ---------------------------------------------------------------------------
__global__ void __launch_bounds__(128)
attn_kernel()
{
    const int T = 64;                         // key tile
    const int chunks = Sn / 128;              // 8
    const int bh = blockIdx.x / chunks;       // 0..63
    const int qc = blockIdx.x % chunks;
    const int b = bh >> 3, h = bh & 7;
    const int qrow = qc * 128 + threadIdx.x;

    const float* base = g_qkv + (size_t)b * Sn * QKVN + h * (3 * HDm);

    float q[64];
    {
        const float4* qp = (const float4*)(base + (size_t)qrow * QKVN);
        #pragma unroll
        for (int c = 0; c < 16; c++) {
            float4 v = qp[c];
            q[4*c+0] = v.x * 0.125f;   // 1/sqrt(64)
            q[4*c+1] = v.y * 0.125f;
            q[4*c+2] = v.z * 0.125f;
            q[4*c+3] = v.w * 0.125f;
        }
    }
    float o[64];
    #pragma unroll
    for (int d = 0; d < 64; d++) o[d] = 0.f;
    float m = -1e30f, l = 0.f;

    __shared__ float4 Ks[T * 16];
    __shared__ float4 Vs[T * 16];

    for (int k0 = 0; k0 < Sn; k0 += T) {
        for (int i = threadIdx.x; i < T * 16; i += 128) {
            int r = i >> 4, c = i & 15;
            const float4* kp = (const float4*)(base + (size_t)(k0 + r) * QKVN + HDm);
            Ks[i] = kp[c];        // K at cols [64,128)
            Vs[i] = kp[16 + c];   // V at cols [128,192)
        }
        __syncthreads();

        for (int j = 0; j < T; j += 2) {
            // ---- two dot products with 4 partial accumulators each ----
            float pa[4] = {0.f, 0.f, 0.f, 0.f};
            float pb[4] = {0.f, 0.f, 0.f, 0.f};
            #pragma unroll
            for (int c = 0; c < 16; c++) {
                float4 ka = Ks[j * 16 + c];          // broadcast
                float4 kb = Ks[(j + 1) * 16 + c];
                pa[0] += q[4*c+0] * ka.x;
                pa[1] += q[4*c+1] * ka.y;
                pa[2] += q[4*c+2] * ka.z;
                pa[3] += q[4*c+3] * ka.w;
                pb[0] += q[4*c+0] * kb.x;
                pb[1] += q[4*c+1] * kb.y;
                pb[2] += q[4*c+2] * kb.z;
                pb[3] += q[4*c+3] * kb.w;
            }
            float sa = (pa[0] + pa[1]) + (pa[2] + pa[3]);
            float sb = (pb[0] + pb[1]) + (pb[2] + pb[3]);

            // ---- one rescale for the pair ----
            float mnew = fmaxf(m, fmaxf(sa, sb));
            if (mnew > m) {
                float corr = __expf(m - mnew);
                l *= corr;
                #pragma unroll
                for (int d = 0; d < 64; d++) o[d] *= corr;
                m = mnew;
            }
            float ea = __expf(sa - m);
            float eb = __expf(sb - m);
            l += ea + eb;

            #pragma unroll
            for (int c = 0; c < 16; c++) {
                float4 va = Vs[j * 16 + c];
                float4 vb = Vs[(j + 1) * 16 + c];
                o[4*c+0] += ea * va.x + eb * vb.x;
                o[4*c+1] += ea * va.y + eb * vb.y;
                o[4*c+2] += ea * va.z + eb * vb.z;
                o[4*c+3] += ea * va.w + eb * vb.w;
            }
        }
        __syncthreads();
    }

    const float invl = 1.f / l;
    float4* op = (float4*)(g_attn + (size_t)(b * Sn + qrow) * Cn + h * HDm);
    #pragma unroll
    for (int c = 0; c < 16; c++) {
        float4 r;
        r.x = o[4*c+0] * invl;
        r.y = o[4*c+1] * invl;
        r.z = o[4*c+2] * invl;
        r.w = o[4*c+3] * invl;
        op[c] = r;
    }
}

// ---------------------------------------------------------------------------
// Launch: gn -> qkv gemm -> attention -> out gemm (+bias +residual)
// ---------------------------------------------------------------------------
extern "C" void kernel_launch(void* const* d_in, const int* in_sizes, int n_in,
                              void* d_out, int out_size)
{
    const float* x        = (const float*)d_in[0];
    // d_in[1] = t, unused by the reference computation
    const float* gn_scale = (const float*)d_in[2];
    const float* gn_bias  = (const float*)d_in[3];
    const float* w_qkv    = (const float*)d_in[4];
    const float* b_qkv    = (const float*)d_in[5];
    const float* w_out    = (const float*)d_in[6];
    const float* b_out    = (const float*)d_in[7];
    float* out = (float*)d_out;

    float *qkv_p = nullptr, *attn_p = nullptr;
    cudaGetSymbolAddress((void**)&qkv_p,  g_qkv);
    cudaGetSymbolAddress((void**)&attn_p, g_attn);

    // 1) GroupNorm -> xn lives in d_out (used as GEMM-A input and as residual)
    gn_kernel<<<Bn * Gn, 256>>>(x, gn_scale, gn_bias, out);

    // 2) QKV projection: [8192,512] @ [512,1536] + b_qkv
    {
        dim3 grid(QKVN / 128, MROWS / 128);
        sgemm_kernel<false><<<grid, 256>>>(out, w_qkv, b_qkv, nullptr, qkv_p,
                                           MROWS, QKVN, Cn);
    }

    // 3) Attention: g_qkv -> g_attn [8192,512]
    attn_kernel<<<Bn * NH * (Sn / 128), 128>>>();

    // 4) Output projection + bias + residual(xn) -> d_out
    {
        dim3 grid(Cn / 128, MROWS / 128);
        sgemm_kernel<true><<<grid, 256>>>(attn_p, w_out, b_out, out, out,
                                          MROWS, Cn, Cn);
    }
}